// round 16
// baseline (speedup 1.0000x reference)
#include <cuda_runtime.h>
#include <cuda_fp16.h>
#include <math_constants.h>

#define NNODES 50000
#define EEDGES 800000
#define ETOT   (EEDGES + NNODES)
#define FIN    128
#define HC     128
#define NHEAD  2
#define NCLS   16
#define NEG    0.2f
#define WPB    8
#define GEMM_BLKS ((NNODES + 127) / 128)           // 391
#define CNT_BLKS  ((ETOT + 255) / 256)             // 3321
#define XS_STRIDE 36
#define WS_STRIDE 136
#define EQ     ((ETOT + 3) / 4)                     // quarter segment

// ---------------- scratch ----------------
__device__ __half g_hh[(size_t)NNODES * HC];   // 12.8 MB, gather source
__device__ float  g_asrc[NNODES * NHEAD];
__device__ float  g_adst[NNODES * NHEAD];
__device__ int    g_cnt[NNODES];
__device__ int    g_off[NNODES];
__device__ int    g_csrc[ETOT];
__device__ int    g_es[ETOT];
__device__ int    g_ed[ETOT];
__device__ int    g_rank[ETOT];
__device__ int    g_total;
__device__ int    g_idx64;

__device__ __forceinline__ void load_edge(const void* ei, int t, int& s, int& d) {
    if (t >= EEDGES) { s = d = t - EEDGES; return; }
    if (g_idx64) {
        const long long* p = (const long long*)ei;
        s = (int)p[t]; d = (int)p[EEDGES + t];
    } else {
        const int* p = (const int*)ei;
        s = p[t]; d = p[EEDGES + t];
    }
}

__device__ __forceinline__ unsigned f2tf(float f) {
    unsigned r;
    asm("cvt.rna.tf32.f32 %0, %1;" : "=r"(r) : "f"(f));
    return r;
}

__device__ __forceinline__ void mma_tf32(float* c, const unsigned* a, const unsigned* b) {
    asm volatile(
        "mma.sync.aligned.m16n8k8.row.col.f32.tf32.tf32.f32 "
        "{%0,%1,%2,%3}, {%4,%5,%6,%7}, {%8,%9}, {%0,%1,%2,%3};"
        : "+f"(c[0]), "+f"(c[1]), "+f"(c[2]), "+f"(c[3])
        : "r"(a[0]), "r"(a[1]), "r"(a[2]), "r"(a[3]), "r"(b[0]), "r"(b[1]));
}

// ---------------- init ------------------------------------------------------
__global__ void k_init(const void* ei) {
    int i = blockIdx.x * blockDim.x + threadIdx.x;
    if (i < NNODES) g_cnt[i] = 0;
    if (i == 0) g_total = 0;
    if (blockIdx.x == 0 && threadIdx.x < 32) {
        const long long* p = (const long long*)ei;
        int ok = 1;
        #pragma unroll
        for (int r = 0; r < 8; r++) {
            long long v = p[threadIdx.x + r * 32];
            if (v < 0 || v >= NNODES) ok = 0;
        }
        ok = __all_sync(0xffffffffu, ok);
        if (threadIdx.x == 0) g_idx64 = ok;
    }
}

// ---------------- fused: [tf32 MMA h=x@W + att epilogue] || [edge count] ----
__global__ void __launch_bounds__(256, 2)
k_gemm_count(const float* __restrict__ x, const float* __restrict__ W,
             const float* __restrict__ att_src, const float* __restrict__ att_dst,
             const void* __restrict__ ei) {
    __shared__ unsigned xs[128 * XS_STRIDE];
    __shared__ unsigned ws[32 * WS_STRIDE];
    int tid = threadIdx.x;

    if (blockIdx.x >= GEMM_BLKS) {
        int t = (blockIdx.x - GEMM_BLKS) * 256 + tid;
        if (t < ETOT) {
            int s, d; load_edge(ei, t, s, d);
            g_es[t] = s; g_ed[t] = d;
            g_rank[t] = atomicAdd(&g_cnt[d], 1);
        }
        return;
    }

    int row0 = blockIdx.x * 128;
    int wid = tid >> 5, lane = tid & 31;
    int wr = wid >> 1;
    int wc = wid & 1;
    int grp = lane >> 2;
    int tig = lane & 3;

    float c[2][8][4] = {};

    for (int kt = 0; kt < FIN; kt += 32) {
        #pragma unroll
        for (int it = 0; it < 4; it++) {
            int lin = tid + it * 256;
            int r = lin >> 3, kk4 = (lin & 7) << 2;
            int gr = row0 + r;
            float4 v = make_float4(0.f, 0.f, 0.f, 0.f);
            if (gr < NNODES) v = *(const float4*)&x[(size_t)gr * FIN + kt + kk4];
            unsigned* dst = &xs[r * XS_STRIDE + kk4];
            dst[0] = f2tf(v.x); dst[1] = f2tf(v.y); dst[2] = f2tf(v.z); dst[3] = f2tf(v.w);
        }
        #pragma unroll
        for (int it = 0; it < 4; it++) {
            int lin = tid + it * 256;
            int k = lin >> 5, cc4 = (lin & 31) << 2;
            float4 v = *(const float4*)&W[(size_t)(kt + k) * HC + cc4];
            unsigned* dst = &ws[k * WS_STRIDE + cc4];
            dst[0] = f2tf(v.x); dst[1] = f2tf(v.y); dst[2] = f2tf(v.z); dst[3] = f2tf(v.w);
        }
        __syncthreads();

        #pragma unroll
        for (int kk = 0; kk < 32; kk += 8) {
            unsigned a[2][4];
            #pragma unroll
            for (int mi = 0; mi < 2; mi++) {
                int r = wr * 32 + mi * 16 + grp;
                int k = kk + tig;
                a[mi][0] = xs[r * XS_STRIDE + k];
                a[mi][1] = xs[(r + 8) * XS_STRIDE + k];
                a[mi][2] = xs[r * XS_STRIDE + k + 4];
                a[mi][3] = xs[(r + 8) * XS_STRIDE + k + 4];
            }
            unsigned b[8][2];
            #pragma unroll
            for (int ni = 0; ni < 8; ni++) {
                int col = wc * 64 + ni * 8 + grp;
                int k = kk + tig;
                b[ni][0] = ws[k * WS_STRIDE + col];
                b[ni][1] = ws[(k + 4) * WS_STRIDE + col];
            }
            #pragma unroll
            for (int mi = 0; mi < 2; mi++)
                #pragma unroll
                for (int ni = 0; ni < 8; ni++)
                    mma_tf32(c[mi][ni], a[mi], b[ni]);
        }
        __syncthreads();
    }

    float as0[8], as1[8], ad0[8], ad1[8];
    #pragma unroll
    for (int ni = 0; ni < 8; ni++) {
        int col = wc * 64 + ni * 8 + tig * 2;
        as0[ni] = att_src[col];     as1[ni] = att_src[col + 1];
        ad0[ni] = att_dst[col];     ad1[ni] = att_dst[col + 1];
    }

    #pragma unroll
    for (int mi = 0; mi < 2; mi++) {
        int gr_lo = row0 + wr * 32 + mi * 16 + grp;
        int gr_hi = gr_lo + 8;
        float ps_lo = 0.f, ps_hi = 0.f, pd_lo = 0.f, pd_hi = 0.f;
        #pragma unroll
        for (int ni = 0; ni < 8; ni++) {
            const float* cc = c[mi][ni];
            ps_lo += cc[0] * as0[ni] + cc[1] * as1[ni];
            pd_lo += cc[0] * ad0[ni] + cc[1] * ad1[ni];
            ps_hi += cc[2] * as0[ni] + cc[3] * as1[ni];
            pd_hi += cc[2] * ad0[ni] + cc[3] * ad1[ni];
            int col = wc * 64 + ni * 8 + tig * 2;
            if (gr_lo < NNODES) {
                __half2 h = __float22half2_rn(make_float2(cc[0], cc[1]));
                *(__half2*)&g_hh[(size_t)gr_lo * HC + col] = h;
            }
            if (gr_hi < NNODES) {
                __half2 h = __float22half2_rn(make_float2(cc[2], cc[3]));
                *(__half2*)&g_hh[(size_t)gr_hi * HC + col] = h;
            }
        }
        #pragma unroll
        for (int o = 1; o < 4; o <<= 1) {
            ps_lo += __shfl_xor_sync(0xffffffffu, ps_lo, o);
            pd_lo += __shfl_xor_sync(0xffffffffu, pd_lo, o);
            ps_hi += __shfl_xor_sync(0xffffffffu, ps_hi, o);
            pd_hi += __shfl_xor_sync(0xffffffffu, pd_hi, o);
        }
        if (tig == 0) {
            if (gr_lo < NNODES) {
                g_asrc[gr_lo * 2 + wc] = ps_lo;
                g_adst[gr_lo * 2 + wc] = pd_lo;
            }
            if (gr_hi < NNODES) {
                g_asrc[gr_hi * 2 + wc] = ps_hi;
                g_adst[gr_hi * 2 + wc] = pd_hi;
            }
        }
    }
}

// ---------------- warp-aggregated bucket allocation -------------------------
__global__ void k_alloc() {
    int i = blockIdx.x * blockDim.x + threadIdx.x;
    int lane = threadIdx.x & 31;
    int cnt = (i < NNODES) ? g_cnt[i] : 0;
    int pre = cnt;
    #pragma unroll
    for (int o = 1; o < 32; o <<= 1) {
        int v = __shfl_up_sync(0xffffffffu, pre, o);
        if (lane >= o) pre += v;
    }
    int tot = __shfl_sync(0xffffffffu, pre, 31);
    int base = 0;
    if (lane == 31) base = atomicAdd(&g_total, tot);
    base = __shfl_sync(0xffffffffu, base, 31);
    if (i < NNODES) g_off[i] = base + pre - cnt;
}

// ---------------- fill: 4 independent edges per thread (MLP=4) --------------
__global__ void k_fill() {
    int t = blockIdx.x * blockDim.x + threadIdx.x;
    if (t >= EQ) return;
    int t0 = t, t1 = t + EQ, t2 = t + 2 * EQ, t3 = t + 3 * EQ;
    bool h1 = (t1 < ETOT), h2 = (t2 < ETOT), h3 = (t3 < ETOT);

    int d0 = g_ed[t0];
    int d1 = h1 ? g_ed[t1] : 0;
    int d2 = h2 ? g_ed[t2] : 0;
    int d3 = h3 ? g_ed[t3] : 0;

    int o0 = g_off[d0];
    int o1 = h1 ? g_off[d1] : 0;
    int o2 = h2 ? g_off[d2] : 0;
    int o3 = h3 ? g_off[d3] : 0;

    int r0 = g_rank[t0];
    int r1 = h1 ? g_rank[t1] : 0;
    int r2 = h2 ? g_rank[t2] : 0;
    int r3 = h3 ? g_rank[t3] : 0;

    int s0 = g_es[t0];
    int s1 = h1 ? g_es[t1] : 0;
    int s2 = h2 ? g_es[t2] : 0;
    int s3 = h3 ? g_es[t3] : 0;

    g_csrc[o0 + r0] = s0;
    if (h1) g_csrc[o1 + r1] = s1;
    if (h2) g_csrc[o2 + r2] = s2;
    if (h3) g_csrc[o3 + r3] = s3;
}

// ---------------- fused softmax-aggregate + bias/relu/fc/log_softmax --------
__global__ void k_agg(const float* __restrict__ bias, const float* __restrict__ Wfc,
                      const float* __restrict__ bfc, float* __restrict__ out) {
    __shared__ float wt[NCLS * HC];
    __shared__ int   sh_s[WPB][32];
    __shared__ float sh_w0[WPB][32];
    __shared__ float sh_w1[WPB][32];
    int tid = threadIdx.x;
    for (int i = tid; i < NCLS * HC; i += blockDim.x) {
        int c = i >> 7, k = i & 127;
        wt[i] = Wfc[k * NCLS + c];
    }
    __syncthreads();

    int wid = tid >> 5, lane = tid & 31;
    int node = blockIdx.x * WPB + wid;
    if (node >= NNODES) return;

    int off = g_off[node];
    int deg = g_cnt[node];
    float ad0 = g_adst[node * 2], ad1 = g_adst[node * 2 + 1];
    int head = lane >> 4;

    float acc0 = 0.f, acc1 = 0.f, acc2 = 0.f, acc3 = 0.f, den = 0.f;

    for (int base = 0; base < deg; base += 32) {
        int i = base + lane;
        int s = 0; float w0 = 0.f, w1 = 0.f;
        if (i < deg) {
            s = g_csrc[off + i];
            float2 as = *(const float2*)&g_asrc[s * 2];
            float e0 = as.x + ad0, e1 = as.y + ad1;
            e0 = e0 > 0.f ? e0 : NEG * e0;
            e1 = e1 > 0.f ? e1 : NEG * e1;
            w0 = __expf(e0); w1 = __expf(e1);
        }
        sh_s[wid][lane] = s; sh_w0[wid][lane] = w0; sh_w1[wid][lane] = w1;
        __syncwarp();

        int nthis = deg - base; if (nthis > 32) nthis = 32;
        int nproc = (nthis + 7) & ~7;
        const float* whp = head ? sh_w1[wid] : sh_w0[wid];
        for (int j = 0; j < nproc; j += 8) {
            int se[8]; float we[8];
            #pragma unroll
            for (int p = 0; p < 8; p++) { se[p] = sh_s[wid][j + p]; we[p] = whp[j + p]; }
            uint2 r[8];
            #pragma unroll
            for (int p = 0; p < 8; p++)
                r[p] = *(const uint2*)&g_hh[(size_t)se[p] * HC + lane * 4];
            #pragma unroll
            for (int p = 0; p < 8; p++) {
                float2 f01 = __half22float2(*(__half2*)&r[p].x);
                float2 f23 = __half22float2(*(__half2*)&r[p].y);
                den  += we[p];
                acc0 += f01.x * we[p]; acc1 += f01.y * we[p];
                acc2 += f23.x * we[p]; acc3 += f23.y * we[p];
            }
        }
        __syncwarp();
    }

    float inv = 1.f / (den + 1e-16f);
    float4 bv = *(const float4*)&bias[lane * 4];
    float v0 = fmaxf(acc0 * inv + bv.x, 0.f);
    float v1 = fmaxf(acc1 * inv + bv.y, 0.f);
    float v2 = fmaxf(acc2 * inv + bv.z, 0.f);
    float v3 = fmaxf(acc3 * inv + bv.w, 0.f);

    float fa[NCLS];
    int k0 = lane * 4;
    #pragma unroll
    for (int c = 0; c < NCLS; c++) {
        float4 w4 = *(const float4*)&wt[c * HC + k0];
        fa[c] = v0 * w4.x + v1 * w4.y + v2 * w4.z + v3 * w4.w;
    }

    // halving-butterfly: 16 sums across 32 lanes in 16 shfls.
    float r8[8];
    #pragma unroll
    for (int i = 0; i < 8; i++) {
        float send = (lane & 1) ? fa[i] : fa[i + 8];
        float recv = __shfl_xor_sync(0xffffffffu, send, 1);
        r8[i] = ((lane & 1) ? fa[i + 8] : fa[i]) + recv;
    }
    float r4[4];
    #pragma unroll
    for (int i = 0; i < 4; i++) {
        float send = (lane & 2) ? r8[i] : r8[i + 4];
        float recv = __shfl_xor_sync(0xffffffffu, send, 2);
        r4[i] = ((lane & 2) ? r8[i + 4] : r8[i]) + recv;
    }
    float r2[2];
    #pragma unroll
    for (int i = 0; i < 2; i++) {
        float send = (lane & 4) ? r4[i] : r4[i + 2];
        float recv = __shfl_xor_sync(0xffffffffu, send, 4);
        r2[i] = ((lane & 4) ? r4[i + 2] : r4[i]) + recv;
    }
    float r1;
    {
        float send = (lane & 8) ? r2[0] : r2[1];
        float recv = __shfl_xor_sync(0xffffffffu, send, 8);
        r1 = ((lane & 8) ? r2[1] : r2[0]) + recv;
    }
    r1 += __shfl_xor_sync(0xffffffffu, r1, 16);

    int cls = ((lane & 1) << 3) | (((lane >> 1) & 1) << 2)
            | (((lane >> 2) & 1) << 1) | ((lane >> 3) & 1);
    float s = r1 + bfc[cls];

    float m = s;
    #pragma unroll
    for (int o = 1; o < 16; o <<= 1) m = fmaxf(m, __shfl_xor_sync(0xffffffffu, m, o));
    float e = __expf(s - m);
    float se = e;
    #pragma unroll
    for (int o = 1; o < 16; o <<= 1) se += __shfl_xor_sync(0xffffffffu, se, o);
    float res = s - (m + logf(se));
    if (lane < 16) out[(size_t)node * NCLS + cls] = res;
}

// ---------------- launch ----------------------------------------------------
extern "C" void kernel_launch(void* const* d_in, const int* in_sizes, int n_in,
                              void* d_out, int out_size) {
    const float* x       = (const float*)d_in[0];
    const void*  ei      = d_in[1];
    const float* W       = (const float*)d_in[2];
    const float* att_src = (const float*)d_in[3];
    const float* att_dst = (const float*)d_in[4];
    const float* bias    = (const float*)d_in[5];
    const float* Wfc     = (const float*)d_in[6];
    const float* bfc     = (const float*)d_in[7];
    float* out = (float*)d_out;

    k_init<<<(NNODES + 255) / 256, 256>>>(ei);
    k_gemm_count<<<GEMM_BLKS + CNT_BLKS, 256>>>(x, W, att_src, att_dst, ei);
    k_alloc<<<(NNODES + 255) / 256, 256>>>();
    k_fill<<<(EQ + 255) / 256, 256>>>();
    k_agg<<<(NNODES + WPB - 1) / WPB, 256>>>(bias, Wfc, bfc, out);
}

// round 17
// speedup vs baseline: 1.0197x; 1.0197x over previous
#include <cuda_runtime.h>
#include <cuda_fp16.h>
#include <math_constants.h>

#define NNODES 50000
#define EEDGES 800000
#define ETOT   (EEDGES + NNODES)
#define FIN    128
#define HC     128
#define NHEAD  2
#define NCLS   16
#define NEG    0.2f
#define WPB    8
#define GEMM_BLKS ((NNODES + 127) / 128)           // 391
#define CNT_BLKS  ((ETOT + 255) / 256)             // 3321
#define XS_STRIDE 36
#define WS_STRIDE 136

// ---------------- scratch ----------------
__device__ __half g_hh[(size_t)NNODES * HC];   // 12.8 MB, gather source
__device__ float  g_asrc[NNODES * NHEAD];
__device__ float  g_adst[NNODES * NHEAD];
__device__ int    g_cnt[NNODES];               // zero at start; alloc re-zeroes
__device__ int2   g_offdeg[NNODES];            // {bucket base, degree}
__device__ int    g_csrc[ETOT];
__device__ int    g_es[ETOT];
__device__ int    g_ed[ETOT];
__device__ int    g_rank[ETOT];
__device__ int    g_total;                     // zeroed by k_detect
__device__ int    g_idx64;

__device__ __forceinline__ void load_edge(const void* ei, int t, int& s, int& d) {
    if (t >= EEDGES) { s = d = t - EEDGES; return; }
    if (g_idx64) {
        const long long* p = (const long long*)ei;
        s = (int)p[t]; d = (int)p[EEDGES + t];
    } else {
        const int* p = (const int*)ei;
        s = p[t]; d = p[EEDGES + t];
    }
}

__device__ __forceinline__ unsigned f2tf(float f) {
    unsigned r;
    asm("cvt.rna.tf32.f32 %0, %1;" : "=r"(r) : "f"(f));
    return r;
}

__device__ __forceinline__ void mma_tf32(float* c, const unsigned* a, const unsigned* b) {
    asm volatile(
        "mma.sync.aligned.m16n8k8.row.col.f32.tf32.tf32.f32 "
        "{%0,%1,%2,%3}, {%4,%5,%6,%7}, {%8,%9}, {%0,%1,%2,%3};"
        : "+f"(c[0]), "+f"(c[1]), "+f"(c[2]), "+f"(c[3])
        : "r"(a[0]), "r"(a[1]), "r"(a[2]), "r"(a[3]), "r"(b[0]), "r"(b[1]));
}

// ---------------- detect index width + reset allocator cursor ---------------
__global__ void k_detect(const void* ei) {
    if (threadIdx.x < 32) {
        const long long* p = (const long long*)ei;
        int ok = 1;
        #pragma unroll
        for (int r = 0; r < 8; r++) {
            long long v = p[threadIdx.x + r * 32];
            if (v < 0 || v >= NNODES) ok = 0;
        }
        ok = __all_sync(0xffffffffu, ok);
        if (threadIdx.x == 0) { g_idx64 = ok; g_total = 0; }
    }
}

// ---------------- fused: [tf32 MMA h=x@W + att epilogue] || [edge count] ----
__global__ void __launch_bounds__(256, 2)
k_gemm_count(const float* __restrict__ x, const float* __restrict__ W,
             const float* __restrict__ att_src, const float* __restrict__ att_dst,
             const void* __restrict__ ei) {
    __shared__ unsigned xs[128 * XS_STRIDE];
    __shared__ unsigned ws[32 * WS_STRIDE];
    int tid = threadIdx.x;

    if (blockIdx.x >= GEMM_BLKS) {
        int t = (blockIdx.x - GEMM_BLKS) * 256 + tid;
        if (t < ETOT) {
            int s, d; load_edge(ei, t, s, d);
            g_es[t] = s; g_ed[t] = d;
            g_rank[t] = atomicAdd(&g_cnt[d], 1);
        }
        return;
    }

    int row0 = blockIdx.x * 128;
    int wid = tid >> 5, lane = tid & 31;
    int wr = wid >> 1;
    int wc = wid & 1;
    int grp = lane >> 2;
    int tig = lane & 3;

    float c[2][8][4] = {};

    for (int kt = 0; kt < FIN; kt += 32) {
        #pragma unroll
        for (int it = 0; it < 4; it++) {
            int lin = tid + it * 256;
            int r = lin >> 3, kk4 = (lin & 7) << 2;
            int gr = row0 + r;
            float4 v = make_float4(0.f, 0.f, 0.f, 0.f);
            if (gr < NNODES) v = *(const float4*)&x[(size_t)gr * FIN + kt + kk4];
            unsigned* dst = &xs[r * XS_STRIDE + kk4];
            dst[0] = f2tf(v.x); dst[1] = f2tf(v.y); dst[2] = f2tf(v.z); dst[3] = f2tf(v.w);
        }
        #pragma unroll
        for (int it = 0; it < 4; it++) {
            int lin = tid + it * 256;
            int k = lin >> 5, cc4 = (lin & 31) << 2;
            float4 v = *(const float4*)&W[(size_t)(kt + k) * HC + cc4];
            unsigned* dst = &ws[k * WS_STRIDE + cc4];
            dst[0] = f2tf(v.x); dst[1] = f2tf(v.y); dst[2] = f2tf(v.z); dst[3] = f2tf(v.w);
        }
        __syncthreads();

        #pragma unroll
        for (int kk = 0; kk < 32; kk += 8) {
            unsigned a[2][4];
            #pragma unroll
            for (int mi = 0; mi < 2; mi++) {
                int r = wr * 32 + mi * 16 + grp;
                int k = kk + tig;
                a[mi][0] = xs[r * XS_STRIDE + k];
                a[mi][1] = xs[(r + 8) * XS_STRIDE + k];
                a[mi][2] = xs[r * XS_STRIDE + k + 4];
                a[mi][3] = xs[(r + 8) * XS_STRIDE + k + 4];
            }
            unsigned b[8][2];
            #pragma unroll
            for (int ni = 0; ni < 8; ni++) {
                int col = wc * 64 + ni * 8 + grp;
                int k = kk + tig;
                b[ni][0] = ws[k * WS_STRIDE + col];
                b[ni][1] = ws[(k + 4) * WS_STRIDE + col];
            }
            #pragma unroll
            for (int mi = 0; mi < 2; mi++)
                #pragma unroll
                for (int ni = 0; ni < 8; ni++)
                    mma_tf32(c[mi][ni], a[mi], b[ni]);
        }
        __syncthreads();
    }

    float as0[8], as1[8], ad0[8], ad1[8];
    #pragma unroll
    for (int ni = 0; ni < 8; ni++) {
        int col = wc * 64 + ni * 8 + tig * 2;
        as0[ni] = att_src[col];     as1[ni] = att_src[col + 1];
        ad0[ni] = att_dst[col];     ad1[ni] = att_dst[col + 1];
    }

    #pragma unroll
    for (int mi = 0; mi < 2; mi++) {
        int gr_lo = row0 + wr * 32 + mi * 16 + grp;
        int gr_hi = gr_lo + 8;
        float ps_lo = 0.f, ps_hi = 0.f, pd_lo = 0.f, pd_hi = 0.f;
        #pragma unroll
        for (int ni = 0; ni < 8; ni++) {
            const float* cc = c[mi][ni];
            ps_lo += cc[0] * as0[ni] + cc[1] * as1[ni];
            pd_lo += cc[0] * ad0[ni] + cc[1] * ad1[ni];
            ps_hi += cc[2] * as0[ni] + cc[3] * as1[ni];
            pd_hi += cc[2] * ad0[ni] + cc[3] * ad1[ni];
            int col = wc * 64 + ni * 8 + tig * 2;
            if (gr_lo < NNODES) {
                __half2 h = __float22half2_rn(make_float2(cc[0], cc[1]));
                *(__half2*)&g_hh[(size_t)gr_lo * HC + col] = h;
            }
            if (gr_hi < NNODES) {
                __half2 h = __float22half2_rn(make_float2(cc[2], cc[3]));
                *(__half2*)&g_hh[(size_t)gr_hi * HC + col] = h;
            }
        }
        #pragma unroll
        for (int o = 1; o < 4; o <<= 1) {
            ps_lo += __shfl_xor_sync(0xffffffffu, ps_lo, o);
            pd_lo += __shfl_xor_sync(0xffffffffu, pd_lo, o);
            ps_hi += __shfl_xor_sync(0xffffffffu, ps_hi, o);
            pd_hi += __shfl_xor_sync(0xffffffffu, pd_hi, o);
        }
        if (tig == 0) {
            if (gr_lo < NNODES) {
                g_asrc[gr_lo * 2 + wc] = ps_lo;
                g_adst[gr_lo * 2 + wc] = pd_lo;
            }
            if (gr_hi < NNODES) {
                g_asrc[gr_hi * 2 + wc] = ps_hi;
                g_adst[gr_hi * 2 + wc] = pd_hi;
            }
        }
    }
}

// ---------------- bucket allocation + counter reset + metadata pack ---------
__global__ void k_alloc() {
    int i = blockIdx.x * blockDim.x + threadIdx.x;
    int lane = threadIdx.x & 31;
    int cnt = (i < NNODES) ? g_cnt[i] : 0;
    int pre = cnt;
    #pragma unroll
    for (int o = 1; o < 32; o <<= 1) {
        int v = __shfl_up_sync(0xffffffffu, pre, o);
        if (lane >= o) pre += v;
    }
    int tot = __shfl_sync(0xffffffffu, pre, 31);
    int base = 0;
    if (lane == 31) base = atomicAdd(&g_total, tot);
    base = __shfl_sync(0xffffffffu, base, 31);
    if (i < NNODES) {
        g_offdeg[i] = make_int2(base + pre - cnt, cnt);
        g_cnt[i] = 0;                      // restore invariant for next replay
    }
}

// ---------------- fill: atomic-free via precomputed rank --------------------
__global__ void k_fill() {
    int t = blockIdx.x * blockDim.x + threadIdx.x;
    if (t >= ETOT) return;
    int d = g_ed[t];
    g_csrc[g_offdeg[d].x + g_rank[t]] = g_es[t];
}

// ---------------- fused softmax-aggregate + bias/relu/fc/log_softmax --------
__global__ void k_agg(const float* __restrict__ bias, const float* __restrict__ Wfc,
                      const float* __restrict__ bfc, float* __restrict__ out) {
    __shared__ float wt[NCLS * HC];
    __shared__ int   sh_s[WPB][32];
    __shared__ float sh_w0[WPB][32];
    __shared__ float sh_w1[WPB][32];
    int tid = threadIdx.x;
    for (int i = tid; i < NCLS * HC; i += blockDim.x) {
        int c = i >> 7, k = i & 127;
        wt[i] = Wfc[k * NCLS + c];
    }
    __syncthreads();

    int wid = tid >> 5, lane = tid & 31;
    int node = blockIdx.x * WPB + wid;
    if (node >= NNODES) return;

    int2 od = g_offdeg[node];
    int off = od.x, deg = od.y;
    float ad0 = g_adst[node * 2], ad1 = g_adst[node * 2 + 1];
    int head = lane >> 4;

    float acc0 = 0.f, acc1 = 0.f, acc2 = 0.f, acc3 = 0.f, den = 0.f;

    for (int base = 0; base < deg; base += 32) {
        int i = base + lane;
        int s = 0; float w0 = 0.f, w1 = 0.f;
        if (i < deg) {
            s = g_csrc[off + i];
            float2 as = *(const float2*)&g_asrc[s * 2];
            float e0 = as.x + ad0, e1 = as.y + ad1;
            e0 = e0 > 0.f ? e0 : NEG * e0;
            e1 = e1 > 0.f ? e1 : NEG * e1;
            w0 = __expf(e0); w1 = __expf(e1);
        }
        sh_s[wid][lane] = s; sh_w0[wid][lane] = w0; sh_w1[wid][lane] = w1;
        __syncwarp();

        int nthis = deg - base; if (nthis > 32) nthis = 32;
        int nproc = (nthis + 7) & ~7;
        const float* whp = head ? sh_w1[wid] : sh_w0[wid];
        for (int j = 0; j < nproc; j += 8) {
            int se[8]; float we[8];
            #pragma unroll
            for (int p = 0; p < 8; p++) { se[p] = sh_s[wid][j + p]; we[p] = whp[j + p]; }
            uint2 r[8];
            #pragma unroll
            for (int p = 0; p < 8; p++)
                r[p] = *(const uint2*)&g_hh[(size_t)se[p] * HC + lane * 4];
            #pragma unroll
            for (int p = 0; p < 8; p++) {
                float2 f01 = __half22float2(*(__half2*)&r[p].x);
                float2 f23 = __half22float2(*(__half2*)&r[p].y);
                den  += we[p];
                acc0 += f01.x * we[p]; acc1 += f01.y * we[p];
                acc2 += f23.x * we[p]; acc3 += f23.y * we[p];
            }
        }
        __syncwarp();
    }

    float inv = 1.f / (den + 1e-16f);
    float4 bv = *(const float4*)&bias[lane * 4];
    float v0 = fmaxf(acc0 * inv + bv.x, 0.f);
    float v1 = fmaxf(acc1 * inv + bv.y, 0.f);
    float v2 = fmaxf(acc2 * inv + bv.z, 0.f);
    float v3 = fmaxf(acc3 * inv + bv.w, 0.f);

    float fa[NCLS];
    int k0 = lane * 4;
    #pragma unroll
    for (int c = 0; c < NCLS; c++) {
        float4 w4 = *(const float4*)&wt[c * HC + k0];
        fa[c] = v0 * w4.x + v1 * w4.y + v2 * w4.z + v3 * w4.w;
    }

    // halving-butterfly: 16 sums across 32 lanes in 16 shfls.
    float r8[8];
    #pragma unroll
    for (int i = 0; i < 8; i++) {
        float send = (lane & 1) ? fa[i] : fa[i + 8];
        float recv = __shfl_xor_sync(0xffffffffu, send, 1);
        r8[i] = ((lane & 1) ? fa[i + 8] : fa[i]) + recv;
    }
    float r4[4];
    #pragma unroll
    for (int i = 0; i < 4; i++) {
        float send = (lane & 2) ? r8[i] : r8[i + 4];
        float recv = __shfl_xor_sync(0xffffffffu, send, 2);
        r4[i] = ((lane & 2) ? r8[i + 4] : r8[i]) + recv;
    }
    float r2[2];
    #pragma unroll
    for (int i = 0; i < 2; i++) {
        float send = (lane & 4) ? r4[i] : r4[i + 2];
        float recv = __shfl_xor_sync(0xffffffffu, send, 4);
        r2[i] = ((lane & 4) ? r4[i + 2] : r4[i]) + recv;
    }
    float r1;
    {
        float send = (lane & 8) ? r2[0] : r2[1];
        float recv = __shfl_xor_sync(0xffffffffu, send, 8);
        r1 = ((lane & 8) ? r2[1] : r2[0]) + recv;
    }
    r1 += __shfl_xor_sync(0xffffffffu, r1, 16);

    int cls = ((lane & 1) << 3) | (((lane >> 1) & 1) << 2)
            | (((lane >> 2) & 1) << 1) | ((lane >> 3) & 1);
    float s = r1 + bfc[cls];

    float m = s;
    #pragma unroll
    for (int o = 1; o < 16; o <<= 1) m = fmaxf(m, __shfl_xor_sync(0xffffffffu, m, o));
    float e = __expf(s - m);
    float se = e;
    #pragma unroll
    for (int o = 1; o < 16; o <<= 1) se += __shfl_xor_sync(0xffffffffu, se, o);
    float res = s - (m + logf(se));
    if (lane < 16) out[(size_t)node * NCLS + cls] = res;
}

// ---------------- launch ----------------------------------------------------
extern "C" void kernel_launch(void* const* d_in, const int* in_sizes, int n_in,
                              void* d_out, int out_size) {
    const float* x       = (const float*)d_in[0];
    const void*  ei      = d_in[1];
    const float* W       = (const float*)d_in[2];
    const float* att_src = (const float*)d_in[3];
    const float* att_dst = (const float*)d_in[4];
    const float* bias    = (const float*)d_in[5];
    const float* Wfc     = (const float*)d_in[6];
    const float* bfc     = (const float*)d_in[7];
    float* out = (float*)d_out;

    k_detect<<<1, 32>>>(ei);
    k_gemm_count<<<GEMM_BLKS + CNT_BLKS, 256>>>(x, W, att_src, att_dst, ei);
    k_alloc<<<(NNODES + 255) / 256, 256>>>();
    k_fill<<<(ETOT + 255) / 256, 256>>>();
    k_agg<<<(NNODES + WPB - 1) / WPB, 256>>>(bias, Wfc, bfc, out);
}